// round 3
// baseline (speedup 1.0000x reference)
#include <cuda_runtime.h>
#include <cuda_bf16.h>
#include <cstdint>
#include <cstddef>

#define NREF 50000
#define NQ   25000
#define NE   400000

// ---------------- scratch (device globals; no allocation allowed) ------------
__device__ __align__(16) float g_tmp_ref [NREF * 128];  // ref_feat @ Wf0 (raw, pre-BN)
__device__ __align__(16) float g_tmp_skip[NQ   * 128];  // query_feat @ Ws0 (raw)
__device__ __align__(16) float g_x1      [NQ   * 128];  // relu(query_f + bn(skip))
__device__ __align__(16) float g_y1      [NQ   * 256];  // x1 @ W1 (raw, pre-BN)
__device__ float g_w[NE];
__device__ float g_wsum[NQ];
__device__ int   g_cnt[NQ];
__device__ int   g_off[NQ + 1];
__device__ int   g_cursor[NQ];
__device__ int   g_eperm[NE];
__device__ float g_colsum[4 * 256];
__device__ float g_colsq [4 * 256];
__device__ __align__(16) float g_bns[4 * 256];   // BN scale per layer
__device__ __align__(16) float g_bnt[4 * 256];   // BN shift per layer

// ---------------- f32x2 helpers ----------------------------------------------
__device__ __forceinline__ unsigned long long splat2(float v) {
    unsigned long long r;
    asm("mov.b64 %0, {%1, %1};" : "=l"(r) : "r"(__float_as_uint(v)));
    return r;
}
__device__ __forceinline__ void fma2(unsigned long long& d, unsigned long long a,
                                     unsigned long long b) {
#if __CUDA_ARCH__ >= 1000
    asm("fma.rn.f32x2 %0, %1, %2, %3;" : "=l"(d) : "l"(a), "l"(b), "l"(d));
#else
    unsigned alo, ahi, blo, bhi, dlo, dhi;
    asm("mov.b64 {%0,%1}, %2;" : "=r"(alo), "=r"(ahi) : "l"(a));
    asm("mov.b64 {%0,%1}, %2;" : "=r"(blo), "=r"(bhi) : "l"(b));
    asm("mov.b64 {%0,%1}, %2;" : "=r"(dlo), "=r"(dhi) : "l"(d));
    float x = fmaf(__uint_as_float(alo), __uint_as_float(blo), __uint_as_float(dlo));
    float y = fmaf(__uint_as_float(ahi), __uint_as_float(bhi), __uint_as_float(dhi));
    asm("mov.b64 %0, {%1,%2};" : "=l"(d) : "r"(__float_as_uint(x)), "r"(__float_as_uint(y)));
#endif
}
__device__ __forceinline__ float2 unpack2(unsigned long long v) {
    unsigned lo, hi;
    asm("mov.b64 {%0, %1}, %2;" : "=r"(lo), "=r"(hi) : "l"(v));
    return make_float2(__uint_as_float(lo), __uint_as_float(hi));
}

// ---------------- init --------------------------------------------------------
__global__ void zero_kernel() {
    int i = blockIdx.x * blockDim.x + threadIdx.x;
    if (i < NQ) { g_wsum[i] = 0.f; g_cnt[i] = 0; g_cursor[i] = 0; }
    if (i < 4 * 256) { g_colsum[i] = 0.f; g_colsq[i] = 0.f; }
}

// ---------------- edge weights + per-query histogram -------------------------
__global__ void edge_w_kernel(const float* __restrict__ ref_bxyz,
                              const float* __restrict__ query_bxyz,
                              const int* __restrict__ e_ref,
                              const int* __restrict__ e_query) {
    int e = blockIdx.x * blockDim.x + threadIdx.x;
    if (e >= NE) return;
    int r = e_ref[e], q = e_query[e];
    float4 rb = ((const float4*)ref_bxyz)[r];
    float4 qb = ((const float4*)query_bxyz)[q];
    float dx = rb.y - qb.y, dy = rb.z - qb.z, dz = rb.w - qb.w;
    float dist = sqrtf(dx * dx + dy * dy + dz * dz);
    float w = 1.0f / (dist + 1e-8f);
    g_w[e] = w;
    atomicAdd(&g_wsum[q], w);
    atomicAdd(&g_cnt[q], 1);
}

// ---------------- single-block exclusive scan over g_cnt ---------------------
__global__ void scan_kernel() {
    __shared__ int buf[1024];
    __shared__ int s_carry;
    int tid = threadIdx.x;
    if (tid == 0) s_carry = 0;
    __syncthreads();
    const int nch = (NQ + 1023) / 1024;
    for (int ch = 0; ch < nch; ++ch) {
        int i = ch * 1024 + tid;
        int v = (i < NQ) ? g_cnt[i] : 0;
        buf[tid] = v;
        __syncthreads();
        for (int d = 1; d < 1024; d <<= 1) {
            int t = (tid >= d) ? buf[tid - d] : 0;
            __syncthreads();
            buf[tid] += t;
            __syncthreads();
        }
        int incl = buf[tid];
        int carry = s_carry;
        if (i < NQ) g_off[i] = carry + incl - v;
        __syncthreads();
        if (tid == 1023) s_carry = carry + incl;
        __syncthreads();
    }
    if (tid == 0) g_off[NQ] = s_carry;
}

__global__ void fill_kernel(const int* __restrict__ e_query) {
    int e = blockIdx.x * blockDim.x + threadIdx.x;
    if (e >= NE) return;
    int q = e_query[e];
    int pos = g_off[q] + atomicAdd(&g_cursor[q], 1);
    g_eperm[pos] = e;
}

// ---------------- warp-per-query gather: x1 = relu(query_f + bn(skip)) -------
__global__ void gather_kernel(const int* __restrict__ e_ref) {
    int warp = (blockIdx.x * blockDim.x + threadIdx.x) >> 5;
    int lane = threadIdx.x & 31;
    if (warp >= NQ) return;
    int q = warp;
    int beg = g_off[q], end = g_off[q + 1];
    float inv = 1.0f / g_wsum[q];
    float4 s0 = ((const float4*)(g_bns))[lane];
    float4 t0 = ((const float4*)(g_bnt))[lane];
    float4 s1 = ((const float4*)(g_bns + 256))[lane];
    float4 t1 = ((const float4*)(g_bnt + 256))[lane];
    float4 acc = make_float4(0.f, 0.f, 0.f, 0.f);
    for (int i = beg; i < end; ++i) {
        int e = g_eperm[i];
        float w = g_w[e] * inv;
        int r = e_ref[e];
        float4 v = *(const float4*)(g_tmp_ref + (size_t)r * 128 + lane * 4);
        acc.x += w * (v.x * s0.x + t0.x);
        acc.y += w * (v.y * s0.y + t0.y);
        acc.z += w * (v.z * s0.z + t0.z);
        acc.w += w * (v.w * s0.w + t0.w);
    }
    float4 sv = *(const float4*)(g_tmp_skip + (size_t)q * 128 + lane * 4);
    float4 o;
    o.x = fmaxf(acc.x + sv.x * s1.x + t1.x, 0.f);
    o.y = fmaxf(acc.y + sv.y * s1.y + t1.y, 0.f);
    o.z = fmaxf(acc.z + sv.z * s1.z + t1.z, 0.f);
    o.w = fmaxf(acc.w + sv.w * s1.w + t1.w, 0.f);
    *(float4*)(g_x1 + (size_t)q * 128 + lane * 4) = o;
}

// ---------------- BN params: s = g*rsqrt(var+eps), t = b - mean*s -------------
__global__ void bnparams_kernel(int layer, int N, float Minv,
                                const float* __restrict__ g,
                                const float* __restrict__ b) {
    int c = threadIdx.x;
    if (c >= N) return;
    float mean = g_colsum[layer * 256 + c] * Minv;
    float msq  = g_colsq [layer * 256 + c] * Minv;
    float var  = msq - mean * mean;
    float s = g[c] * rsqrtf(var + 1e-5f);
    g_bns[layer * 256 + c] = s;
    g_bnt[layer * 256 + c] = b[c] - mean * s;
}

// ---------------- GEMM (f32x2 packed FFMA), fused column stats ---------------
// C[M,N_] = A[M,K_] @ W[K_,N_]; optional BN+relu transform on A load (SRC==2).
// SRC: 0=ext A, 1=g_x1, 2=g_y1 (apply bn layer2 + relu on load)
// DST: 0=ext C, 1=g_tmp_ref, 2=g_tmp_skip, 3=g_y1
template <int K_, int N_, int LAYER, int SRC, int DST>
__global__ void __launch_bounds__(8 * (N_ / 8))
gemm_kernel(const float* __restrict__ Aext, const float* __restrict__ W,
            float* __restrict__ Cext, int M) {
    constexpr int BM = 64, BK = 16;
    constexpr int NT = 8 * (N_ / 8);
    __shared__ __align__(16) unsigned long long As[BK][BM];  // pair-splatted
    __shared__ __align__(16) float Bs[BK][N_];
    __shared__ float redS[N_];
    __shared__ float redQ[N_];

    const float* Ap = (SRC == 0) ? Aext : (SRC == 1 ? g_x1 : g_y1);
    float* Cp = (DST == 0) ? Cext : (DST == 1 ? g_tmp_ref : (DST == 2 ? g_tmp_skip : g_y1));
    const float* ts = &g_bns[2 * 256];
    const float* tt = &g_bnt[2 * 256];

    int tid = threadIdx.x;
    int tx = tid % (N_ / 8);
    int ty = tid / (N_ / 8);
    int m0 = blockIdx.x * BM;

    unsigned long long acc[8][4];
#pragma unroll
    for (int i = 0; i < 8; ++i)
#pragma unroll
        for (int j = 0; j < 4; ++j) acc[i][j] = 0ull;

    for (int kb = 0; kb < K_ / BK; ++kb) {
        int k0 = kb * BK;
        // A tile -> splatted pairs, transposed
        for (int idx = tid; idx < BM * BK / 4; idx += NT) {
            int r = idx >> 2;
            int kq = idx & 3;
            int row = m0 + r;
            float4 v = make_float4(0.f, 0.f, 0.f, 0.f);
            if (row < M) {
                v = *(const float4*)(Ap + (size_t)row * K_ + k0 + kq * 4);
                if (SRC == 2) {
                    int c = k0 + kq * 4;
                    v.x = fmaxf(v.x * ts[c + 0] + tt[c + 0], 0.f);
                    v.y = fmaxf(v.y * ts[c + 1] + tt[c + 1], 0.f);
                    v.z = fmaxf(v.z * ts[c + 2] + tt[c + 2], 0.f);
                    v.w = fmaxf(v.w * ts[c + 3] + tt[c + 3], 0.f);
                }
            }
            As[kq * 4 + 0][r] = splat2(v.x);
            As[kq * 4 + 1][r] = splat2(v.y);
            As[kq * 4 + 2][r] = splat2(v.z);
            As[kq * 4 + 3][r] = splat2(v.w);
        }
        // B tile
        for (int idx = tid; idx < BK * N_ / 4; idx += NT) {
            int kr = idx / (N_ / 4);
            int c4 = idx % (N_ / 4);
            *(float4*)&Bs[kr][c4 * 4] =
                *(const float4*)(W + (size_t)(k0 + kr) * N_ + c4 * 4);
        }
        __syncthreads();
#pragma unroll
        for (int kk = 0; kk < BK; ++kk) {
            ulonglong2 a0 = *(const ulonglong2*)&As[kk][ty * 8 + 0];
            ulonglong2 a1 = *(const ulonglong2*)&As[kk][ty * 8 + 2];
            ulonglong2 a2 = *(const ulonglong2*)&As[kk][ty * 8 + 4];
            ulonglong2 a3 = *(const ulonglong2*)&As[kk][ty * 8 + 6];
            ulonglong2 b0 = *(const ulonglong2*)&Bs[kk][tx * 8 + 0];
            ulonglong2 b1 = *(const ulonglong2*)&Bs[kk][tx * 8 + 4];
            unsigned long long av[8] = {a0.x, a0.y, a1.x, a1.y, a2.x, a2.y, a3.x, a3.y};
            unsigned long long bv[4] = {b0.x, b0.y, b1.x, b1.y};
#pragma unroll
            for (int i = 0; i < 8; ++i)
#pragma unroll
                for (int j = 0; j < 4; ++j) fma2(acc[i][j], av[i], bv[j]);
        }
        __syncthreads();
    }

    // unpack
    float cr[8][8];
#pragma unroll
    for (int i = 0; i < 8; ++i)
#pragma unroll
        for (int j = 0; j < 4; ++j) {
            float2 p = unpack2(acc[i][j]);
            cr[i][2 * j + 0] = p.x;
            cr[i][2 * j + 1] = p.y;
        }

    // fused column stats (padded rows contribute exact zeros)
    for (int idx = tid; idx < N_; idx += NT) { redS[idx] = 0.f; redQ[idx] = 0.f; }
    __syncthreads();
#pragma unroll
    for (int jj = 0; jj < 8; ++jj) {
        float ps = 0.f, pq = 0.f;
#pragma unroll
        for (int i = 0; i < 8; ++i) { float v = cr[i][jj]; ps += v; pq += v * v; }
        atomicAdd(&redS[tx * 8 + jj], ps);
        atomicAdd(&redQ[tx * 8 + jj], pq);
    }
    __syncthreads();
    for (int idx = tid; idx < N_; idx += NT) {
        atomicAdd(&g_colsum[LAYER * 256 + idx], redS[idx]);
        atomicAdd(&g_colsq [LAYER * 256 + idx], redQ[idx]);
    }

    // store C
#pragma unroll
    for (int i = 0; i < 8; ++i) {
        int row = m0 + ty * 8 + i;
        if (row < M) {
            float4 v0 = make_float4(cr[i][0], cr[i][1], cr[i][2], cr[i][3]);
            float4 v1 = make_float4(cr[i][4], cr[i][5], cr[i][6], cr[i][7]);
            *(float4*)(Cp + (size_t)row * N_ + tx * 8 + 0) = v0;
            *(float4*)(Cp + (size_t)row * N_ + tx * 8 + 4) = v1;
        }
    }
}

// ---------------- final in-place BN + relu on d_out --------------------------
__global__ void final_kernel(float* __restrict__ out) {
    int i = blockIdx.x * blockDim.x + threadIdx.x;
    if (i >= NQ * 256) return;
    int c = i & 255;
    float v = out[i];
    out[i] = fmaxf(v * g_bns[3 * 256 + c] + g_bnt[3 * 256 + c], 0.f);
}

// ---------------- launch ------------------------------------------------------
extern "C" void kernel_launch(void* const* d_in, const int* in_sizes, int n_in,
                              void* d_out, int out_size) {
    const float* ref_bxyz   = (const float*)d_in[0];
    const float* ref_feat   = (const float*)d_in[1];
    const float* query_bxyz = (const float*)d_in[2];
    const float* query_feat = (const float*)d_in[3];
    const int*   e_ref      = (const int*)d_in[4];
    const int*   e_query    = (const int*)d_in[5];
    const float* Wf0   = (const float*)d_in[6];
    const float* gf0   = (const float*)d_in[7];
    const float* bf0   = (const float*)d_in[8];
    const float* Ws0   = (const float*)d_in[9];
    const float* gs0   = (const float*)d_in[10];
    const float* bs0   = (const float*)d_in[11];
    const float* W1    = (const float*)d_in[12];
    // b1 = d_in[13]: cancels exactly through training-mode BN
    const float* g1    = (const float*)d_in[14];
    const float* beta1 = (const float*)d_in[15];
    const float* W2    = (const float*)d_in[16];
    // b2 = d_in[17]: cancels exactly through training-mode BN
    const float* g2    = (const float*)d_in[18];
    const float* beta2 = (const float*)d_in[19];
    float* out = (float*)d_out;

    zero_kernel<<<(NQ + 255) / 256, 256>>>();
    edge_w_kernel<<<(NE + 255) / 256, 256>>>(ref_bxyz, query_bxyz, e_ref, e_query);

    // branch GEMMs + column stats
    gemm_kernel<128, 128, 0, 0, 1><<<(NREF + 63) / 64, 128>>>(ref_feat,  Wf0, nullptr, NREF);
    gemm_kernel<128, 128, 1, 0, 2><<<(NQ   + 63) / 64, 128>>>(query_feat, Ws0, nullptr, NQ);
    bnparams_kernel<<<1, 256>>>(0, 128, 1.0f / NREF, gf0, bf0);
    bnparams_kernel<<<1, 256>>>(1, 128, 1.0f / NQ,   gs0, bs0);

    // CSR build + gather
    scan_kernel<<<1, 1024>>>();
    fill_kernel<<<(NE + 255) / 256, 256>>>(e_query);
    gather_kernel<<<(NQ * 32 + 255) / 256, 256>>>(e_ref);

    // MLP layer 1
    gemm_kernel<128, 256, 2, 1, 3><<<(NQ + 63) / 64, 256>>>(nullptr, W1, nullptr, NQ);
    bnparams_kernel<<<1, 256>>>(2, 256, 1.0f / NQ, g1, beta1);

    // MLP layer 2 (bn1+relu fused into A-load), writes raw y2 into d_out
    gemm_kernel<256, 256, 3, 2, 0><<<(NQ + 63) / 64, 256>>>(nullptr, W2, out, NQ);
    bnparams_kernel<<<1, 256>>>(3, 256, 1.0f / NQ, g2, beta2);

    // final BN + relu in place
    final_kernel<<<(NQ * 256 + 255) / 256, 256>>>(out);
}

// round 8
// speedup vs baseline: 1.3500x; 1.3500x over previous
#include <cuda_runtime.h>
#include <cuda_bf16.h>
#include <cstdint>
#include <cstddef>

#define NREF 50000
#define NQ   25000
#define NE   400000

// ---------------- scratch (device globals; no allocation allowed) ------------
__device__ __align__(16) float g_tmp_ref [NREF * 128];  // ref_feat @ Wf0 (raw, pre-BN)
__device__ __align__(16) float g_tmp_skip[NQ   * 128];  // query_feat @ Ws0 (raw)
__device__ __align__(16) float g_x1      [NQ   * 128];  // relu(query_f + bn(skip))
__device__ __align__(16) float g_y1      [NQ   * 256];  // x1 @ W1 (raw, pre-BN)
__device__ float g_w[NE];
__device__ float g_wsum[NQ];
__device__ int   g_cnt[NQ];
__device__ int   g_off[NQ + 1];
__device__ int   g_cursor[NQ];
__device__ int   g_eperm[NE];
__device__ float g_colsum[4 * 256];
__device__ float g_colsq [4 * 256];
__device__ __align__(16) float g_bns[4 * 256];   // BN scale per layer
__device__ __align__(16) float g_bnt[4 * 256];   // BN shift per layer

// ---------------- f32x2 helpers ----------------------------------------------
__device__ __forceinline__ unsigned long long splat2(float v) {
    unsigned long long r;
    asm("mov.b64 %0, {%1, %1};" : "=l"(r) : "r"(__float_as_uint(v)));
    return r;
}
__device__ __forceinline__ void fma2(unsigned long long& d, unsigned long long a,
                                     unsigned long long b) {
#if __CUDA_ARCH__ >= 1000
    asm("fma.rn.f32x2 %0, %1, %2, %3;" : "=l"(d) : "l"(a), "l"(b), "l"(d));
#else
    unsigned alo, ahi, blo, bhi, dlo, dhi;
    asm("mov.b64 {%0,%1}, %2;" : "=r"(alo), "=r"(ahi) : "l"(a));
    asm("mov.b64 {%0,%1}, %2;" : "=r"(blo), "=r"(bhi) : "l"(b));
    asm("mov.b64 {%0,%1}, %2;" : "=r"(dlo), "=r"(dhi) : "l"(d));
    float x = fmaf(__uint_as_float(alo), __uint_as_float(blo), __uint_as_float(dlo));
    float y = fmaf(__uint_as_float(ahi), __uint_as_float(bhi), __uint_as_float(dhi));
    asm("mov.b64 %0, {%1,%2};" : "=l"(d) : "r"(__float_as_uint(x)), "r"(__float_as_uint(y)));
#endif
}
__device__ __forceinline__ float2 unpack2(unsigned long long v) {
    unsigned lo, hi;
    asm("mov.b64 {%0, %1}, %2;" : "=r"(lo), "=r"(hi) : "l"(v));
    return make_float2(__uint_as_float(lo), __uint_as_float(hi));
}

// ---------------- init --------------------------------------------------------
__global__ void zero_kernel() {
    int i = blockIdx.x * blockDim.x + threadIdx.x;
    if (i < NQ) { g_wsum[i] = 0.f; g_cnt[i] = 0; g_cursor[i] = 0; }
    if (i < 4 * 256) { g_colsum[i] = 0.f; g_colsq[i] = 0.f; }
}

// ---------------- edge weights + per-query histogram -------------------------
__global__ void edge_w_kernel(const float* __restrict__ ref_bxyz,
                              const float* __restrict__ query_bxyz,
                              const int* __restrict__ e_ref,
                              const int* __restrict__ e_query) {
    int e = blockIdx.x * blockDim.x + threadIdx.x;
    if (e >= NE) return;
    int r = e_ref[e], q = e_query[e];
    float4 rb = ((const float4*)ref_bxyz)[r];
    float4 qb = ((const float4*)query_bxyz)[q];
    float dx = rb.y - qb.y, dy = rb.z - qb.z, dz = rb.w - qb.w;
    float dist = sqrtf(dx * dx + dy * dy + dz * dz);
    float w = 1.0f / (dist + 1e-8f);
    g_w[e] = w;
    atomicAdd(&g_wsum[q], w);
    atomicAdd(&g_cnt[q], 1);
}

// ---------------- single-block exclusive scan over g_cnt ---------------------
__global__ void scan_kernel() {
    __shared__ int buf[1024];
    __shared__ int s_carry;
    int tid = threadIdx.x;
    if (tid == 0) s_carry = 0;
    __syncthreads();
    const int nch = (NQ + 1023) / 1024;
    for (int ch = 0; ch < nch; ++ch) {
        int i = ch * 1024 + tid;
        int v = (i < NQ) ? g_cnt[i] : 0;
        buf[tid] = v;
        __syncthreads();
        for (int d = 1; d < 1024; d <<= 1) {
            int t = (tid >= d) ? buf[tid - d] : 0;
            __syncthreads();
            buf[tid] += t;
            __syncthreads();
        }
        int incl = buf[tid];
        int carry = s_carry;
        if (i < NQ) g_off[i] = carry + incl - v;
        __syncthreads();
        if (tid == 1023) s_carry = carry + incl;
        __syncthreads();
    }
    if (tid == 0) g_off[NQ] = s_carry;
}

__global__ void fill_kernel(const int* __restrict__ e_query) {
    int e = blockIdx.x * blockDim.x + threadIdx.x;
    if (e >= NE) return;
    int q = e_query[e];
    int pos = g_off[q] + atomicAdd(&g_cursor[q], 1);
    g_eperm[pos] = e;
}

// ---------------- warp-per-query gather: x1 = relu(query_f + bn(skip)) -------
__global__ void gather_kernel(const int* __restrict__ e_ref) {
    int warp = (blockIdx.x * blockDim.x + threadIdx.x) >> 5;
    int lane = threadIdx.x & 31;
    if (warp >= NQ) return;
    int q = warp;
    int beg = g_off[q], end = g_off[q + 1];
    float inv = 1.0f / g_wsum[q];
    float4 s0 = ((const float4*)(g_bns))[lane];
    float4 t0 = ((const float4*)(g_bnt))[lane];
    float4 s1 = ((const float4*)(g_bns + 256))[lane];
    float4 t1 = ((const float4*)(g_bnt + 256))[lane];
    float4 acc = make_float4(0.f, 0.f, 0.f, 0.f);
    for (int i = beg; i < end; ++i) {
        int e = g_eperm[i];
        float w = g_w[e] * inv;
        int r = e_ref[e];
        float4 v = *(const float4*)(g_tmp_ref + (size_t)r * 128 + lane * 4);
        acc.x += w * (v.x * s0.x + t0.x);
        acc.y += w * (v.y * s0.y + t0.y);
        acc.z += w * (v.z * s0.z + t0.z);
        acc.w += w * (v.w * s0.w + t0.w);
    }
    float4 sv = *(const float4*)(g_tmp_skip + (size_t)q * 128 + lane * 4);
    float4 o;
    o.x = fmaxf(acc.x + sv.x * s1.x + t1.x, 0.f);
    o.y = fmaxf(acc.y + sv.y * s1.y + t1.y, 0.f);
    o.z = fmaxf(acc.z + sv.z * s1.z + t1.z, 0.f);
    o.w = fmaxf(acc.w + sv.w * s1.w + t1.w, 0.f);
    *(float4*)(g_x1 + (size_t)q * 128 + lane * 4) = o;
}

// ---------------- BN params: s = g*rsqrt(var+eps), t = b - mean*s -------------
__global__ void bnparams_kernel(int layer, int N, float Minv,
                                const float* __restrict__ g,
                                const float* __restrict__ b) {
    int c = threadIdx.x;
    if (c >= N) return;
    float mean = g_colsum[layer * 256 + c] * Minv;
    float msq  = g_colsq [layer * 256 + c] * Minv;
    float var  = msq - mean * mean;
    float s = g[c] * rsqrtf(var + 1e-5f);
    g_bns[layer * 256 + c] = s;
    g_bnt[layer * 256 + c] = b[c] - mean * s;
}

// ---------------- GEMM (f32x2 packed FFMA), fused column stats ---------------
// C[M,N_] = A[M,K_] @ W[K_,N_]; optional BN+relu transform on A load (SRC==2).
// SRC: 0=ext A, 1=g_x1, 2=g_y1 (apply bn layer2 + relu on load)
// DST: 0=ext C, 1=g_tmp_ref, 2=g_tmp_skip, 3=g_y1
// Block: 128 threads, tile BM=64 x BN=128. N_ > 128 handled via blockIdx.y.
// A kept as scalar floats in smem; pair-splat happens in registers (ALU pipe)
// to cut LDS bytes/FFMA2 from 3 to 2.
template <int K_, int N_, int LAYER, int SRC, int DST>
__global__ void __launch_bounds__(128)
gemm_kernel(const float* __restrict__ Aext, const float* __restrict__ W,
            float* __restrict__ Cext, int M) {
    constexpr int BM = 64, BK = 16, BN = 128;
    constexpr int NT = 128;
    static_assert(N_ % BN == 0, "N_ multiple of 128");
    __shared__ __align__(16) float As[BK][BM];
    __shared__ __align__(16) float Bs[BK][BN];
    __shared__ float redS[BN];
    __shared__ float redQ[BN];

    const float* Ap = (SRC == 0) ? Aext : (SRC == 1 ? g_x1 : g_y1);
    float* Cp = (DST == 0) ? Cext : (DST == 1 ? g_tmp_ref : (DST == 2 ? g_tmp_skip : g_y1));
    const float* ts = &g_bns[2 * 256];
    const float* tt = &g_bnt[2 * 256];

    int tid = threadIdx.x;
    int tx = tid & 15;          // 16 col-groups of 8
    int ty = tid >> 4;          // 8 row-groups of 8
    int m0 = blockIdx.x * BM;
    int n0 = blockIdx.y * BN;

    unsigned long long acc[8][4];
#pragma unroll
    for (int i = 0; i < 8; ++i)
#pragma unroll
        for (int j = 0; j < 4; ++j) acc[i][j] = 0ull;

    for (int kb = 0; kb < K_ / BK; ++kb) {
        int k0 = kb * BK;
        // A tile (scalar floats, transposed) — 256 float4 items / 128 threads
#pragma unroll
        for (int it = 0; it < 2; ++it) {
            int idx = it * NT + tid;
            int r = idx >> 2;
            int kq = idx & 3;
            int row = m0 + r;
            float4 v = make_float4(0.f, 0.f, 0.f, 0.f);
            if (row < M) {
                v = *(const float4*)(Ap + (size_t)row * K_ + k0 + kq * 4);
                if (SRC == 2) {
                    int c = k0 + kq * 4;
                    v.x = fmaxf(v.x * ts[c + 0] + tt[c + 0], 0.f);
                    v.y = fmaxf(v.y * ts[c + 1] + tt[c + 1], 0.f);
                    v.z = fmaxf(v.z * ts[c + 2] + tt[c + 2], 0.f);
                    v.w = fmaxf(v.w * ts[c + 3] + tt[c + 3], 0.f);
                }
            }
            As[kq * 4 + 0][r] = v.x;
            As[kq * 4 + 1][r] = v.y;
            As[kq * 4 + 2][r] = v.z;
            As[kq * 4 + 3][r] = v.w;
        }
        // B tile: BK*BN/4 = 512 float4-items / 128 threads = 4 iters
#pragma unroll
        for (int it = 0; it < 4; ++it) {
            int idx = it * NT + tid;
            int kr = idx / (BN / 4);
            int c4 = idx % (BN / 4);
            *(float4*)&Bs[kr][c4 * 4] =
                *(const float4*)(W + (size_t)(k0 + kr) * N_ + n0 + c4 * 4);
        }
        __syncthreads();
#pragma unroll
        for (int kk = 0; kk < BK; ++kk) {
            float4 af0 = *(const float4*)&As[kk][ty * 8 + 0];
            float4 af1 = *(const float4*)&As[kk][ty * 8 + 4];
            ulonglong2 b0 = *(const ulonglong2*)&Bs[kk][tx * 8 + 0];
            ulonglong2 b1 = *(const ulonglong2*)&Bs[kk][tx * 8 + 4];
            unsigned long long av[8];
            av[0] = splat2(af0.x); av[1] = splat2(af0.y);
            av[2] = splat2(af0.z); av[3] = splat2(af0.w);
            av[4] = splat2(af1.x); av[5] = splat2(af1.y);
            av[6] = splat2(af1.z); av[7] = splat2(af1.w);
            unsigned long long bv[4] = {b0.x, b0.y, b1.x, b1.y};
#pragma unroll
            for (int i = 0; i < 8; ++i)
#pragma unroll
                for (int j = 0; j < 4; ++j) fma2(acc[i][j], av[i], bv[j]);
        }
        __syncthreads();
    }

    // unpack
    float cr[8][8];
#pragma unroll
    for (int i = 0; i < 8; ++i)
#pragma unroll
        for (int j = 0; j < 4; ++j) {
            float2 p = unpack2(acc[i][j]);
            cr[i][2 * j + 0] = p.x;
            cr[i][2 * j + 1] = p.y;
        }

    // fused column stats (padded rows contribute exact zeros)
    for (int idx = tid; idx < BN; idx += NT) { redS[idx] = 0.f; redQ[idx] = 0.f; }
    __syncthreads();
#pragma unroll
    for (int jj = 0; jj < 8; ++jj) {
        float ps = 0.f, pq = 0.f;
#pragma unroll
        for (int i = 0; i < 8; ++i) { float v = cr[i][jj]; ps += v; pq += v * v; }
        atomicAdd(&redS[tx * 8 + jj], ps);
        atomicAdd(&redQ[tx * 8 + jj], pq);
    }
    __syncthreads();
    for (int idx = tid; idx < BN; idx += NT) {
        atomicAdd(&g_colsum[LAYER * 256 + n0 + idx], redS[idx]);
        atomicAdd(&g_colsq [LAYER * 256 + n0 + idx], redQ[idx]);
    }

    // store C
#pragma unroll
    for (int i = 0; i < 8; ++i) {
        int row = m0 + ty * 8 + i;
        if (row < M) {
            float4 v0 = make_float4(cr[i][0], cr[i][1], cr[i][2], cr[i][3]);
            float4 v1 = make_float4(cr[i][4], cr[i][5], cr[i][6], cr[i][7]);
            *(float4*)(Cp + (size_t)row * N_ + n0 + tx * 8 + 0) = v0;
            *(float4*)(Cp + (size_t)row * N_ + n0 + tx * 8 + 4) = v1;
        }
    }
}

// ---------------- final in-place BN + relu on d_out --------------------------
__global__ void final_kernel(float* __restrict__ out) {
    int i = blockIdx.x * blockDim.x + threadIdx.x;
    if (i >= NQ * 256) return;
    int c = i & 255;
    float v = out[i];
    out[i] = fmaxf(v * g_bns[3 * 256 + c] + g_bnt[3 * 256 + c], 0.f);
}

// ---------------- launch ------------------------------------------------------
extern "C" void kernel_launch(void* const* d_in, const int* in_sizes, int n_in,
                              void* d_out, int out_size) {
    const float* ref_bxyz   = (const float*)d_in[0];
    const float* ref_feat   = (const float*)d_in[1];
    const float* query_bxyz = (const float*)d_in[2];
    const float* query_feat = (const float*)d_in[3];
    const int*   e_ref      = (const int*)d_in[4];
    const int*   e_query    = (const int*)d_in[5];
    const float* Wf0   = (const float*)d_in[6];
    const float* gf0   = (const float*)d_in[7];
    const float* bf0   = (const float*)d_in[8];
    const float* Ws0   = (const float*)d_in[9];
    const float* gs0   = (const float*)d_in[10];
    const float* bs0   = (const float*)d_in[11];
    const float* W1    = (const float*)d_in[12];
    // b1 = d_in[13]: cancels exactly through training-mode BN
    const float* g1    = (const float*)d_in[14];
    const float* beta1 = (const float*)d_in[15];
    const float* W2    = (const float*)d_in[16];
    // b2 = d_in[17]: cancels exactly through training-mode BN
    const float* g2    = (const float*)d_in[18];
    const float* beta2 = (const float*)d_in[19];
    float* out = (float*)d_out;

    zero_kernel<<<(NQ + 255) / 256, 256>>>();
    edge_w_kernel<<<(NE + 255) / 256, 256>>>(ref_bxyz, query_bxyz, e_ref, e_query);

    // branch GEMMs + column stats
    {
        dim3 g0((NREF + 63) / 64, 1);
        gemm_kernel<128, 128, 0, 0, 1><<<g0, 128>>>(ref_feat,  Wf0, nullptr, NREF);
        dim3 g1b((NQ + 63) / 64, 1);
        gemm_kernel<128, 128, 1, 0, 2><<<g1b, 128>>>(query_feat, Ws0, nullptr, NQ);
    }
    bnparams_kernel<<<1, 256>>>(0, 128, 1.0f / NREF, gf0, bf0);
    bnparams_kernel<<<1, 256>>>(1, 128, 1.0f / NQ,   gs0, bs0);

    // CSR build + gather
    scan_kernel<<<1, 1024>>>();
    fill_kernel<<<(NE + 255) / 256, 256>>>(e_query);
    gather_kernel<<<(NQ * 32 + 255) / 256, 256>>>(e_ref);

    // MLP layer 1 (N=256 split over blockIdx.y)
    {
        dim3 g2b((NQ + 63) / 64, 2);
        gemm_kernel<128, 256, 2, 1, 3><<<g2b, 128>>>(nullptr, W1, nullptr, NQ);
    }
    bnparams_kernel<<<1, 256>>>(2, 256, 1.0f / NQ, g1, beta1);

    // MLP layer 2 (bn1+relu fused into A-load), writes raw y2 into d_out
    {
        dim3 g3((NQ + 63) / 64, 2);
        gemm_kernel<256, 256, 3, 2, 0><<<g3, 128>>>(nullptr, W2, out, NQ);
    }
    bnparams_kernel<<<1, 256>>>(3, 256, 1.0f / NQ, g2, beta2);

    // final BN + relu in place
    final_kernel<<<(NQ * 256 + 255) / 256, 256>>>(out);
}

// round 16
// speedup vs baseline: 1.3996x; 1.0367x over previous
#include <cuda_runtime.h>
#include <cuda_bf16.h>
#include <cstdint>
#include <cstddef>

#define NREF 50000
#define NQ   25000
#define NE   400000

// ---------------- scratch (device globals; no allocation allowed) ------------
__device__ __align__(16) float g_tmp_ref [NREF * 128];  // ref_feat @ Wf0 (raw, pre-BN)
__device__ __align__(16) float g_tmp_skip[NQ   * 128];  // query_feat @ Ws0 (raw)
__device__ __align__(16) float g_x1      [NQ   * 128];  // relu(query_f + bn(skip))
__device__ __align__(16) float g_y1      [NQ   * 256];  // x1 @ W1 (raw, pre-BN)
__device__ float g_w[NE];
__device__ float g_wsum[NQ];
__device__ int   g_cnt[NQ];
__device__ int   g_off[NQ + 1];
__device__ int   g_cursor[NQ];
__device__ int   g_eperm[NE];
__device__ float g_colsum[4 * 256];
__device__ float g_colsq [4 * 256];
__device__ __align__(16) float g_bns[4 * 256];   // BN scale per layer
__device__ __align__(16) float g_bnt[4 * 256];   // BN shift per layer

// ---------------- f32x2 helpers ----------------------------------------------
__device__ __forceinline__ unsigned long long splat2(float v) {
    unsigned long long r;
    asm("mov.b64 %0, {%1, %1};" : "=l"(r) : "r"(__float_as_uint(v)));
    return r;
}
__device__ __forceinline__ void fma2(unsigned long long& d, unsigned long long a,
                                     unsigned long long b) {
#if __CUDA_ARCH__ >= 1000
    asm("fma.rn.f32x2 %0, %1, %2, %3;" : "=l"(d) : "l"(a), "l"(b), "l"(d));
#else
    unsigned alo, ahi, blo, bhi, dlo, dhi;
    asm("mov.b64 {%0,%1}, %2;" : "=r"(alo), "=r"(ahi) : "l"(a));
    asm("mov.b64 {%0,%1}, %2;" : "=r"(blo), "=r"(bhi) : "l"(b));
    asm("mov.b64 {%0,%1}, %2;" : "=r"(dlo), "=r"(dhi) : "l"(d));
    float x = fmaf(__uint_as_float(alo), __uint_as_float(blo), __uint_as_float(dlo));
    float y = fmaf(__uint_as_float(ahi), __uint_as_float(bhi), __uint_as_float(dhi));
    asm("mov.b64 %0, {%1,%2};" : "=l"(d) : "r"(__float_as_uint(x)), "r"(__float_as_uint(y)));
#endif
}
__device__ __forceinline__ float2 unpack2(unsigned long long v) {
    unsigned lo, hi;
    asm("mov.b64 {%0, %1}, %2;" : "=r"(lo), "=r"(hi) : "l"(v));
    return make_float2(__uint_as_float(lo), __uint_as_float(hi));
}

// ---------------- init --------------------------------------------------------
__global__ void zero_kernel() {
    int i = blockIdx.x * blockDim.x + threadIdx.x;
    if (i < NQ) { g_wsum[i] = 0.f; g_cnt[i] = 0; g_cursor[i] = 0; }
    if (i < 4 * 256) { g_colsum[i] = 0.f; g_colsq[i] = 0.f; }
}

// ---------------- edge weights + per-query histogram -------------------------
__global__ void edge_w_kernel(const float* __restrict__ ref_bxyz,
                              const float* __restrict__ query_bxyz,
                              const int* __restrict__ e_ref,
                              const int* __restrict__ e_query) {
    int e = blockIdx.x * blockDim.x + threadIdx.x;
    if (e >= NE) return;
    int r = e_ref[e], q = e_query[e];
    float4 rb = ((const float4*)ref_bxyz)[r];
    float4 qb = ((const float4*)query_bxyz)[q];
    float dx = rb.y - qb.y, dy = rb.z - qb.z, dz = rb.w - qb.w;
    float dist = sqrtf(dx * dx + dy * dy + dz * dz);
    float w = 1.0f / (dist + 1e-8f);
    g_w[e] = w;
    atomicAdd(&g_wsum[q], w);
    atomicAdd(&g_cnt[q], 1);
}

// ---------------- single-block exclusive scan over g_cnt ---------------------
__global__ void scan_kernel() {
    __shared__ int buf[1024];
    __shared__ int s_carry;
    int tid = threadIdx.x;
    if (tid == 0) s_carry = 0;
    __syncthreads();
    const int nch = (NQ + 1023) / 1024;
    for (int ch = 0; ch < nch; ++ch) {
        int i = ch * 1024 + tid;
        int v = (i < NQ) ? g_cnt[i] : 0;
        buf[tid] = v;
        __syncthreads();
        for (int d = 1; d < 1024; d <<= 1) {
            int t = (tid >= d) ? buf[tid - d] : 0;
            __syncthreads();
            buf[tid] += t;
            __syncthreads();
        }
        int incl = buf[tid];
        int carry = s_carry;
        if (i < NQ) g_off[i] = carry + incl - v;
        __syncthreads();
        if (tid == 1023) s_carry = carry + incl;
        __syncthreads();
    }
    if (tid == 0) g_off[NQ] = s_carry;
}

__global__ void fill_kernel(const int* __restrict__ e_query) {
    int e = blockIdx.x * blockDim.x + threadIdx.x;
    if (e >= NE) return;
    int q = e_query[e];
    int pos = g_off[q] + atomicAdd(&g_cursor[q], 1);
    g_eperm[pos] = e;
}

// ---------------- warp-per-query gather: x1 = relu(query_f + bn(skip)) -------
__global__ void gather_kernel(const int* __restrict__ e_ref) {
    int warp = (blockIdx.x * blockDim.x + threadIdx.x) >> 5;
    int lane = threadIdx.x & 31;
    if (warp >= NQ) return;
    int q = warp;
    int beg = g_off[q], end = g_off[q + 1];
    float inv = 1.0f / g_wsum[q];
    float4 s0 = ((const float4*)(g_bns))[lane];
    float4 t0 = ((const float4*)(g_bnt))[lane];
    float4 s1 = ((const float4*)(g_bns + 256))[lane];
    float4 t1 = ((const float4*)(g_bnt + 256))[lane];
    float4 acc = make_float4(0.f, 0.f, 0.f, 0.f);
    for (int i = beg; i < end; ++i) {
        int e = g_eperm[i];
        float w = g_w[e] * inv;
        int r = e_ref[e];
        float4 v = *(const float4*)(g_tmp_ref + (size_t)r * 128 + lane * 4);
        acc.x += w * (v.x * s0.x + t0.x);
        acc.y += w * (v.y * s0.y + t0.y);
        acc.z += w * (v.z * s0.z + t0.z);
        acc.w += w * (v.w * s0.w + t0.w);
    }
    float4 sv = *(const float4*)(g_tmp_skip + (size_t)q * 128 + lane * 4);
    float4 o;
    o.x = fmaxf(acc.x + sv.x * s1.x + t1.x, 0.f);
    o.y = fmaxf(acc.y + sv.y * s1.y + t1.y, 0.f);
    o.z = fmaxf(acc.z + sv.z * s1.z + t1.z, 0.f);
    o.w = fmaxf(acc.w + sv.w * s1.w + t1.w, 0.f);
    *(float4*)(g_x1 + (size_t)q * 128 + lane * 4) = o;
}

// ---------------- BN params: s = g*rsqrt(var+eps), t = b - mean*s -------------
__global__ void bnparams_kernel(int layer, int N, float Minv,
                                const float* __restrict__ g,
                                const float* __restrict__ b) {
    int c = threadIdx.x;
    if (c >= N) return;
    float mean = g_colsum[layer * 256 + c] * Minv;
    float msq  = g_colsq [layer * 256 + c] * Minv;
    float var  = msq - mean * mean;
    float s = g[c] * rsqrtf(var + 1e-5f);
    g_bns[layer * 256 + c] = s;
    g_bnt[layer * 256 + c] = b[c] - mean * s;
}

// ---------------- GEMM body (f32x2 FFMA, double-buffered, fused stats) -------
// C[M, N_] = A[M, K_] @ W[K_, N_] over a BM=64 x BN=128 tile at (m0, n0).
// SRCBN=1: apply layer-2 BN + relu on A load. Fused column stats into
// g_colsum/g_colsq[layer]. 2-stage smem pipeline: one __syncthreads per BK-iter;
// next tile's LDG/STS issue into the other stage before computing the current.
template <int K_, int N_, int SRCBN>
__device__ __forceinline__ void gemm_body(
    const float* __restrict__ Ap, const float* __restrict__ W,
    float* __restrict__ Cp, int M, int m0, int n0, int layer,
    float (*As)[16][64], float (*Bs)[16][128],
    float* redS, float* redQ) {
    constexpr int BK = 16, BN = 128, NT = 128;
    constexpr int KB = K_ / BK;

    const float* ts = &g_bns[2 * 256];
    const float* tt = &g_bnt[2 * 256];

    int tid = threadIdx.x;
    int tx = tid & 15;          // 16 col-groups of 8
    int ty = tid >> 4;          // 8 row-groups of 8

    unsigned long long acc[8][4];
#pragma unroll
    for (int i = 0; i < 8; ++i)
#pragma unroll
        for (int j = 0; j < 4; ++j) acc[i][j] = 0ull;

    auto loadA = [&](int s, int k0) {
#pragma unroll
        for (int it = 0; it < 2; ++it) {
            int idx = it * NT + tid;
            int r = idx >> 2;
            int kq = idx & 3;
            int row = m0 + r;
            float4 v = make_float4(0.f, 0.f, 0.f, 0.f);
            if (row < M) {
                v = *(const float4*)(Ap + (size_t)row * K_ + k0 + kq * 4);
                if (SRCBN) {
                    int c = k0 + kq * 4;
                    v.x = fmaxf(v.x * ts[c + 0] + tt[c + 0], 0.f);
                    v.y = fmaxf(v.y * ts[c + 1] + tt[c + 1], 0.f);
                    v.z = fmaxf(v.z * ts[c + 2] + tt[c + 2], 0.f);
                    v.w = fmaxf(v.w * ts[c + 3] + tt[c + 3], 0.f);
                }
            }
            As[s][kq * 4 + 0][r] = v.x;
            As[s][kq * 4 + 1][r] = v.y;
            As[s][kq * 4 + 2][r] = v.z;
            As[s][kq * 4 + 3][r] = v.w;
        }
    };
    auto loadB = [&](int s, int k0) {
#pragma unroll
        for (int it = 0; it < 4; ++it) {
            int idx = it * NT + tid;
            int kr = idx >> 5;          // / 32
            int c4 = idx & 31;          // % 32
            *(float4*)&Bs[s][kr][c4 * 4] =
                *(const float4*)(W + (size_t)(k0 + kr) * N_ + n0 + c4 * 4);
        }
    };

    loadA(0, 0);
    loadB(0, 0);
    __syncthreads();

    for (int kb = 0; kb < KB; ++kb) {
        int st = kb & 1;
        if (kb + 1 < KB) {               // prefetch into the other stage
            loadA(st ^ 1, (kb + 1) * BK);
            loadB(st ^ 1, (kb + 1) * BK);
        }
#pragma unroll
        for (int kk = 0; kk < BK; ++kk) {
            float4 af0 = *(const float4*)&As[st][kk][ty * 8 + 0];
            float4 af1 = *(const float4*)&As[st][kk][ty * 8 + 4];
            ulonglong2 b0 = *(const ulonglong2*)&Bs[st][kk][tx * 8 + 0];
            ulonglong2 b1 = *(const ulonglong2*)&Bs[st][kk][tx * 8 + 4];
            unsigned long long av[8];
            av[0] = splat2(af0.x); av[1] = splat2(af0.y);
            av[2] = splat2(af0.z); av[3] = splat2(af0.w);
            av[4] = splat2(af1.x); av[5] = splat2(af1.y);
            av[6] = splat2(af1.z); av[7] = splat2(af1.w);
            unsigned long long bv[4] = {b0.x, b0.y, b1.x, b1.y};
#pragma unroll
            for (int i = 0; i < 8; ++i)
#pragma unroll
                for (int j = 0; j < 4; ++j) fma2(acc[i][j], av[i], bv[j]);
        }
        __syncthreads();
    }

    // unpack
    float cr[8][8];
#pragma unroll
    for (int i = 0; i < 8; ++i)
#pragma unroll
        for (int j = 0; j < 4; ++j) {
            float2 p = unpack2(acc[i][j]);
            cr[i][2 * j + 0] = p.x;
            cr[i][2 * j + 1] = p.y;
        }

    // fused column stats (padded rows contribute exact zeros)
    for (int idx = tid; idx < BN; idx += NT) { redS[idx] = 0.f; redQ[idx] = 0.f; }
    __syncthreads();
#pragma unroll
    for (int jj = 0; jj < 8; ++jj) {
        float ps = 0.f, pq = 0.f;
#pragma unroll
        for (int i = 0; i < 8; ++i) { float v = cr[i][jj]; ps += v; pq += v * v; }
        atomicAdd(&redS[tx * 8 + jj], ps);
        atomicAdd(&redQ[tx * 8 + jj], pq);
    }
    __syncthreads();
    for (int idx = tid; idx < BN; idx += NT) {
        atomicAdd(&g_colsum[layer * 256 + n0 + idx], redS[idx]);
        atomicAdd(&g_colsq [layer * 256 + n0 + idx], redQ[idx]);
    }

    // store C
#pragma unroll
    for (int i = 0; i < 8; ++i) {
        int row = m0 + ty * 8 + i;
        if (row < M) {
            float4 v0 = make_float4(cr[i][0], cr[i][1], cr[i][2], cr[i][3]);
            float4 v1 = make_float4(cr[i][4], cr[i][5], cr[i][6], cr[i][7]);
            *(float4*)(Cp + (size_t)row * N_ + n0 + tx * 8 + 0) = v0;
            *(float4*)(Cp + (size_t)row * N_ + n0 + tx * 8 + 4) = v1;
        }
    }
}

// ---------------- fused first-layer GEMMs (ref + skip in one grid) ------------
#define RB0 ((NREF + 63) / 64)
#define RB1 ((NQ + 63) / 64)

__global__ void __launch_bounds__(128, 4)
gemm01_kernel(const float* __restrict__ refF, const float* __restrict__ qF,
              const float* __restrict__ Wf0, const float* __restrict__ Ws0) {
    __shared__ __align__(16) float As[2][16][64];
    __shared__ __align__(16) float Bs[2][16][128];
    __shared__ float redS[128];
    __shared__ float redQ[128];
    const float* Ap; const float* W; float* Cp; int M, m0, layer;
    if (blockIdx.x < RB0) {
        Ap = refF; W = Wf0; Cp = g_tmp_ref;  M = NREF; m0 = blockIdx.x * 64;         layer = 0;
    } else {
        Ap = qF;   W = Ws0; Cp = g_tmp_skip; M = NQ;   m0 = (blockIdx.x - RB0) * 64; layer = 1;
    }
    gemm_body<128, 128, 0>(Ap, W, Cp, M, m0, 0, layer, As, Bs, redS, redQ);
}

// ---------------- MLP GEMMs (N=256, BN-tile via blockIdx.y) -------------------
// SRC: 1 = g_x1 (plain), 2 = g_y1 (bn layer2 + relu on load). DST: 0=Cext, 3=g_y1.
template <int K_, int SRC, int DST>
__global__ void __launch_bounds__(128, 4)
gemm256_kernel(const float* __restrict__ W, float* __restrict__ Cext, int M, int layer) {
    __shared__ __align__(16) float As[2][16][64];
    __shared__ __align__(16) float Bs[2][16][128];
    __shared__ float redS[128];
    __shared__ float redQ[128];
    const float* Ap = (SRC == 1) ? g_x1 : g_y1;
    float* Cp = (DST == 0) ? Cext : g_y1;
    gemm_body<K_, 256, (SRC == 2) ? 1 : 0>(Ap, W, Cp, M, blockIdx.x * 64,
                                           blockIdx.y * 128, layer, As, Bs, redS, redQ);
}

// ---------------- final in-place BN + relu on d_out --------------------------
__global__ void final_kernel(float* __restrict__ out) {
    int i = blockIdx.x * blockDim.x + threadIdx.x;
    if (i >= NQ * 256) return;
    int c = i & 255;
    float v = out[i];
    out[i] = fmaxf(v * g_bns[3 * 256 + c] + g_bnt[3 * 256 + c], 0.f);
}

// ---------------- launch ------------------------------------------------------
extern "C" void kernel_launch(void* const* d_in, const int* in_sizes, int n_in,
                              void* d_out, int out_size) {
    const float* ref_bxyz   = (const float*)d_in[0];
    const float* ref_feat   = (const float*)d_in[1];
    const float* query_bxyz = (const float*)d_in[2];
    const float* query_feat = (const float*)d_in[3];
    const int*   e_ref      = (const int*)d_in[4];
    const int*   e_query    = (const int*)d_in[5];
    const float* Wf0   = (const float*)d_in[6];
    const float* gf0   = (const float*)d_in[7];
    const float* bf0   = (const float*)d_in[8];
    const float* Ws0   = (const float*)d_in[9];
    const float* gs0   = (const float*)d_in[10];
    const float* bs0   = (const float*)d_in[11];
    const float* W1    = (const float*)d_in[12];
    // b1 = d_in[13]: cancels exactly through training-mode BN
    const float* g1    = (const float*)d_in[14];
    const float* beta1 = (const float*)d_in[15];
    const float* W2    = (const float*)d_in[16];
    // b2 = d_in[17]: cancels exactly through training-mode BN
    const float* g2    = (const float*)d_in[18];
    const float* beta2 = (const float*)d_in[19];
    float* out = (float*)d_out;

    zero_kernel<<<(NQ + 255) / 256, 256>>>();
    edge_w_kernel<<<(NE + 255) / 256, 256>>>(ref_bxyz, query_bxyz, e_ref, e_query);

    // fused branch GEMMs (one big grid -> full occupancy) + fused column stats
    gemm01_kernel<<<RB0 + RB1, 128>>>(ref_feat, query_feat, Wf0, Ws0);
    bnparams_kernel<<<1, 256>>>(0, 128, 1.0f / NREF, gf0, bf0);
    bnparams_kernel<<<1, 256>>>(1, 128, 1.0f / NQ,   gs0, bs0);

    // CSR build + gather
    scan_kernel<<<1, 1024>>>();
    fill_kernel<<<(NE + 255) / 256, 256>>>(e_query);
    gather_kernel<<<(NQ * 32 + 255) / 256, 256>>>(e_ref);

    // MLP layer 1
    {
        dim3 g2b(RB1, 2);
        gemm256_kernel<128, 1, 3><<<g2b, 128>>>(W1, nullptr, NQ, 2);
    }
    bnparams_kernel<<<1, 256>>>(2, 256, 1.0f / NQ, g1, beta1);

    // MLP layer 2 (bn1+relu fused into A-load), writes raw y2 into d_out
    {
        dim3 g3(RB1, 2);
        gemm256_kernel<256, 2, 0><<<g3, 128>>>(W2, out, NQ, 3);
    }
    bnparams_kernel<<<1, 256>>>(3, 256, 1.0f / NQ, g2, beta2);

    // final BN + relu in place
    final_kernel<<<(NQ * 256 + 255) / 256, 256>>>(out);
}

// round 17
// speedup vs baseline: 1.4591x; 1.0425x over previous
#include <cuda_runtime.h>
#include <cuda_bf16.h>
#include <cstdint>
#include <cstddef>

#define NREF 50000
#define NQ   25000
#define NE   400000

// ---------------- scratch (device globals; no allocation allowed) ------------
__device__ __align__(16) float g_tmp_ref [NREF * 128];  // ref_feat @ Wf0 (raw, pre-BN)
__device__ __align__(16) float g_tmp_skip[NQ   * 128];  // query_feat @ Ws0 (raw)
__device__ __align__(16) float g_x1      [NQ   * 128];  // relu(query_f + bn(skip))
__device__ __align__(16) float g_y1      [NQ   * 256];  // x1 @ W1 (raw, pre-BN)
__device__ float g_w[NE];
__device__ float g_wsum[NQ];
__device__ int   g_cnt[NQ];
__device__ int   g_off[NQ + 1];
__device__ int   g_cursor[NQ];
__device__ int   g_eperm[NE];
__device__ float g_colsum[4 * 256];
__device__ float g_colsq [4 * 256];

// ---------------- f32x2 helpers ----------------------------------------------
__device__ __forceinline__ unsigned long long splat2(float v) {
    unsigned long long r;
    asm("mov.b64 %0, {%1, %1};" : "=l"(r) : "r"(__float_as_uint(v)));
    return r;
}
__device__ __forceinline__ void fma2(unsigned long long& d, unsigned long long a,
                                     unsigned long long b) {
#if __CUDA_ARCH__ >= 1000
    asm("fma.rn.f32x2 %0, %1, %2, %3;" : "=l"(d) : "l"(a), "l"(b), "l"(d));
#else
    unsigned alo, ahi, blo, bhi, dlo, dhi;
    asm("mov.b64 {%0,%1}, %2;" : "=r"(alo), "=r"(ahi) : "l"(a));
    asm("mov.b64 {%0,%1}, %2;" : "=r"(blo), "=r"(bhi) : "l"(b));
    asm("mov.b64 {%0,%1}, %2;" : "=r"(dlo), "=r"(dhi) : "l"(d));
    float x = fmaf(__uint_as_float(alo), __uint_as_float(blo), __uint_as_float(dlo));
    float y = fmaf(__uint_as_float(ahi), __uint_as_float(bhi), __uint_as_float(dhi));
    asm("mov.b64 %0, {%1,%2};" : "=l"(d) : "r"(__float_as_uint(x)), "r"(__float_as_uint(y)));
#endif
}
__device__ __forceinline__ float2 unpack2(unsigned long long v) {
    unsigned lo, hi;
    asm("mov.b64 {%0, %1}, %2;" : "=r"(lo), "=r"(hi) : "l"(v));
    return make_float2(__uint_as_float(lo), __uint_as_float(hi));
}

// BN fold: s = g*rsqrt(var+eps), t = b - mean*s, from raw sum/sumsq
__device__ __forceinline__ float2 bn_st(float sum, float sq, float Minv,
                                        float g, float b) {
    float mean = sum * Minv;
    float var  = sq * Minv - mean * mean;
    float s = g * rsqrtf(var + 1e-5f);
    return make_float2(s, b - mean * s);
}

// ---------------- init --------------------------------------------------------
__global__ void zero_kernel() {
    int i = blockIdx.x * blockDim.x + threadIdx.x;
    if (i < NQ) { g_wsum[i] = 0.f; g_cnt[i] = 0; g_cursor[i] = 0; }
    if (i < 4 * 256) { g_colsum[i] = 0.f; g_colsq[i] = 0.f; }
}

// ---------------- edge weights + per-query histogram -------------------------
__global__ void edge_w_kernel(const float* __restrict__ ref_bxyz,
                              const float* __restrict__ query_bxyz,
                              const int* __restrict__ e_ref,
                              const int* __restrict__ e_query) {
    int e = blockIdx.x * blockDim.x + threadIdx.x;
    if (e >= NE) return;
    int r = e_ref[e], q = e_query[e];
    float4 rb = ((const float4*)ref_bxyz)[r];
    float4 qb = ((const float4*)query_bxyz)[q];
    float dx = rb.y - qb.y, dy = rb.z - qb.z, dz = rb.w - qb.w;
    float dist = sqrtf(dx * dx + dy * dy + dz * dz);
    float w = 1.0f / (dist + 1e-8f);
    g_w[e] = w;
    atomicAdd(&g_wsum[q], w);
    atomicAdd(&g_cnt[q], 1);
}

// ---------------- single-block exclusive scan over g_cnt (warp-shfl) ---------
__global__ void scan_kernel() {
    __shared__ int wsum[32];
    __shared__ int s_carry;
    int tid = threadIdx.x;
    int lane = tid & 31, wid = tid >> 5;
    if (tid == 0) s_carry = 0;
    __syncthreads();
    const int nch = (NQ + 1023) / 1024;
    for (int ch = 0; ch < nch; ++ch) {
        int i = ch * 1024 + tid;
        int v = (i < NQ) ? g_cnt[i] : 0;
        int x = v;
#pragma unroll
        for (int d = 1; d < 32; d <<= 1) {
            int t = __shfl_up_sync(0xFFFFFFFFu, x, d);
            if (lane >= d) x += t;
        }
        if (lane == 31) wsum[wid] = x;
        __syncthreads();
        if (wid == 0) {
            int s = wsum[lane];
#pragma unroll
            for (int d = 1; d < 32; d <<= 1) {
                int t = __shfl_up_sync(0xFFFFFFFFu, s, d);
                if (lane >= d) s += t;
            }
            wsum[lane] = s;
        }
        __syncthreads();
        int base = s_carry + (wid ? wsum[wid - 1] : 0);
        if (i < NQ) g_off[i] = base + x - v;
        __syncthreads();
        if (tid == 1023) s_carry += wsum[31];
        __syncthreads();
    }
    if (tid == 0) g_off[NQ] = s_carry;
}

__global__ void fill_kernel(const int* __restrict__ e_query) {
    int e = blockIdx.x * blockDim.x + threadIdx.x;
    if (e >= NE) return;
    int q = e_query[e];
    int pos = g_off[q] + atomicAdd(&g_cursor[q], 1);
    g_eperm[pos] = e;
}

// ---------------- warp-per-query gather: x1 = relu(query_f + bn(skip)) -------
// BN params for layers 0 (ref) and 1 (skip) computed inline from column stats.
__global__ void gather_kernel(const int* __restrict__ e_ref,
                              const float* __restrict__ gf0, const float* __restrict__ bf0,
                              const float* __restrict__ gs0, const float* __restrict__ bs0) {
    int warp = (blockIdx.x * blockDim.x + threadIdx.x) >> 5;
    int lane = threadIdx.x & 31;
    if (warp >= NQ) return;
    int q = warp;
    int beg = g_off[q], end = g_off[q + 1];
    float inv = 1.0f / g_wsum[q];

    // layer-0 (ref branch) BN params for this lane's 4 channels
    float4 cs = ((const float4*)(g_colsum))[lane];
    float4 cq = ((const float4*)(g_colsq ))[lane];
    float4 gg = ((const float4*)gf0)[lane];
    float4 bb = ((const float4*)bf0)[lane];
    const float MinvR = 1.0f / NREF;
    float2 p;
    p = bn_st(cs.x, cq.x, MinvR, gg.x, bb.x); float s0x = p.x, t0x = p.y;
    p = bn_st(cs.y, cq.y, MinvR, gg.y, bb.y); float s0y = p.x, t0y = p.y;
    p = bn_st(cs.z, cq.z, MinvR, gg.z, bb.z); float s0z = p.x, t0z = p.y;
    p = bn_st(cs.w, cq.w, MinvR, gg.w, bb.w); float s0w = p.x, t0w = p.y;
    // layer-1 (skip branch)
    cs = ((const float4*)(g_colsum + 256))[lane];
    cq = ((const float4*)(g_colsq  + 256))[lane];
    gg = ((const float4*)gs0)[lane];
    bb = ((const float4*)bs0)[lane];
    const float MinvQ = 1.0f / NQ;
    p = bn_st(cs.x, cq.x, MinvQ, gg.x, bb.x); float s1x = p.x, t1x = p.y;
    p = bn_st(cs.y, cq.y, MinvQ, gg.y, bb.y); float s1y = p.x, t1y = p.y;
    p = bn_st(cs.z, cq.z, MinvQ, gg.z, bb.z); float s1z = p.x, t1z = p.y;
    p = bn_st(cs.w, cq.w, MinvQ, gg.w, bb.w); float s1w = p.x, t1w = p.y;

    float4 acc = make_float4(0.f, 0.f, 0.f, 0.f);
    for (int i = beg; i < end; ++i) {
        int e = g_eperm[i];
        float w = g_w[e] * inv;
        int r = e_ref[e];
        float4 v = *(const float4*)(g_tmp_ref + (size_t)r * 128 + lane * 4);
        acc.x += w * (v.x * s0x + t0x);
        acc.y += w * (v.y * s0y + t0y);
        acc.z += w * (v.z * s0z + t0z);
        acc.w += w * (v.w * s0w + t0w);
    }
    float4 sv = *(const float4*)(g_tmp_skip + (size_t)q * 128 + lane * 4);
    float4 o;
    o.x = fmaxf(acc.x + sv.x * s1x + t1x, 0.f);
    o.y = fmaxf(acc.y + sv.y * s1y + t1y, 0.f);
    o.z = fmaxf(acc.z + sv.z * s1z + t1z, 0.f);
    o.w = fmaxf(acc.w + sv.w * s1w + t1w, 0.f);
    *(float4*)(g_x1 + (size_t)q * 128 + lane * 4) = o;
}

// ---------------- GEMM body (f32x2 FFMA, double-buffered, fused stats) -------
// C[M, N_] = A[M, K_] @ W[K_, N_] over a BM=64 x BN=128 tile at (m0, n0).
// ts/tt non-null: apply per-column affine + relu on A load (layer-2 BN folding).
template <int K_, int N_, int SRCBN>
__device__ __forceinline__ void gemm_body(
    const float* __restrict__ Ap, const float* __restrict__ W,
    float* __restrict__ Cp, int M, int m0, int n0, int layer,
    float (*As)[16][64], float (*Bs)[16][128],
    float* redS, float* redQ,
    const float* __restrict__ ts, const float* __restrict__ tt) {
    constexpr int BK = 16, BN = 128, NT = 128;
    constexpr int KB = K_ / BK;

    int tid = threadIdx.x;
    int tx = tid & 15;          // 16 col-groups of 8
    int ty = tid >> 4;          // 8 row-groups of 8

    unsigned long long acc[8][4];
#pragma unroll
    for (int i = 0; i < 8; ++i)
#pragma unroll
        for (int j = 0; j < 4; ++j) acc[i][j] = 0ull;

    auto loadA = [&](int s, int k0) {
#pragma unroll
        for (int it = 0; it < 2; ++it) {
            int idx = it * NT + tid;
            int r = idx >> 2;
            int kq = idx & 3;
            int row = m0 + r;
            float4 v = make_float4(0.f, 0.f, 0.f, 0.f);
            if (row < M) {
                v = *(const float4*)(Ap + (size_t)row * K_ + k0 + kq * 4);
                if (SRCBN) {
                    int c = k0 + kq * 4;
                    v.x = fmaxf(v.x * ts[c + 0] + tt[c + 0], 0.f);
                    v.y = fmaxf(v.y * ts[c + 1] + tt[c + 1], 0.f);
                    v.z = fmaxf(v.z * ts[c + 2] + tt[c + 2], 0.f);
                    v.w = fmaxf(v.w * ts[c + 3] + tt[c + 3], 0.f);
                }
            }
            As[s][kq * 4 + 0][r] = v.x;
            As[s][kq * 4 + 1][r] = v.y;
            As[s][kq * 4 + 2][r] = v.z;
            As[s][kq * 4 + 3][r] = v.w;
        }
    };
    auto loadB = [&](int s, int k0) {
#pragma unroll
        for (int it = 0; it < 4; ++it) {
            int idx = it * NT + tid;
            int kr = idx >> 5;          // / 32
            int c4 = idx & 31;          // % 32
            *(float4*)&Bs[s][kr][c4 * 4] =
                *(const float4*)(W + (size_t)(k0 + kr) * N_ + n0 + c4 * 4);
        }
    };

    loadA(0, 0);
    loadB(0, 0);
    __syncthreads();

    for (int kb = 0; kb < KB; ++kb) {
        int st = kb & 1;
        if (kb + 1 < KB) {               // prefetch into the other stage
            loadA(st ^ 1, (kb + 1) * BK);
            loadB(st ^ 1, (kb + 1) * BK);
        }
#pragma unroll
        for (int kk = 0; kk < BK; ++kk) {
            float4 af0 = *(const float4*)&As[st][kk][ty * 8 + 0];
            float4 af1 = *(const float4*)&As[st][kk][ty * 8 + 4];
            ulonglong2 b0 = *(const ulonglong2*)&Bs[st][kk][tx * 8 + 0];
            ulonglong2 b1 = *(const ulonglong2*)&Bs[st][kk][tx * 8 + 4];
            unsigned long long av[8];
            av[0] = splat2(af0.x); av[1] = splat2(af0.y);
            av[2] = splat2(af0.z); av[3] = splat2(af0.w);
            av[4] = splat2(af1.x); av[5] = splat2(af1.y);
            av[6] = splat2(af1.z); av[7] = splat2(af1.w);
            unsigned long long bv[4] = {b0.x, b0.y, b1.x, b1.y};
#pragma unroll
            for (int i = 0; i < 8; ++i)
#pragma unroll
                for (int j = 0; j < 4; ++j) fma2(acc[i][j], av[i], bv[j]);
        }
        __syncthreads();
    }

    // unpack
    float cr[8][8];
#pragma unroll
    for (int i = 0; i < 8; ++i)
#pragma unroll
        for (int j = 0; j < 4; ++j) {
            float2 p = unpack2(acc[i][j]);
            cr[i][2 * j + 0] = p.x;
            cr[i][2 * j + 1] = p.y;
        }

    // fused column stats (padded rows contribute exact zeros)
    for (int idx = tid; idx < BN; idx += NT) { redS[idx] = 0.f; redQ[idx] = 0.f; }
    __syncthreads();
#pragma unroll
    for (int jj = 0; jj < 8; ++jj) {
        float ps = 0.f, pq = 0.f;
#pragma unroll
        for (int i = 0; i < 8; ++i) { float v = cr[i][jj]; ps += v; pq += v * v; }
        atomicAdd(&redS[tx * 8 + jj], ps);
        atomicAdd(&redQ[tx * 8 + jj], pq);
    }
    __syncthreads();
    for (int idx = tid; idx < BN; idx += NT) {
        atomicAdd(&g_colsum[layer * 256 + n0 + idx], redS[idx]);
        atomicAdd(&g_colsq [layer * 256 + n0 + idx], redQ[idx]);
    }

    // store C
#pragma unroll
    for (int i = 0; i < 8; ++i) {
        int row = m0 + ty * 8 + i;
        if (row < M) {
            float4 v0 = make_float4(cr[i][0], cr[i][1], cr[i][2], cr[i][3]);
            float4 v1 = make_float4(cr[i][4], cr[i][5], cr[i][6], cr[i][7]);
            *(float4*)(Cp + (size_t)row * N_ + n0 + tx * 8 + 0) = v0;
            *(float4*)(Cp + (size_t)row * N_ + n0 + tx * 8 + 4) = v1;
        }
    }
}

// ---------------- fused first-layer GEMMs (ref + skip in one grid) ------------
#define RB0 ((NREF + 63) / 64)
#define RB1 ((NQ + 63) / 64)

__global__ void __launch_bounds__(128, 4)
gemm01_kernel(const float* __restrict__ refF, const float* __restrict__ qF,
              const float* __restrict__ Wf0, const float* __restrict__ Ws0) {
    __shared__ __align__(16) float As[2][16][64];
    __shared__ __align__(16) float Bs[2][16][128];
    __shared__ float redS[128];
    __shared__ float redQ[128];
    const float* Ap; const float* W; float* Cp; int M, m0, layer;
    if (blockIdx.x < RB0) {
        Ap = refF; W = Wf0; Cp = g_tmp_ref;  M = NREF; m0 = blockIdx.x * 64;         layer = 0;
    } else {
        Ap = qF;   W = Ws0; Cp = g_tmp_skip; M = NQ;   m0 = (blockIdx.x - RB0) * 64; layer = 1;
    }
    gemm_body<128, 128, 0>(Ap, W, Cp, M, m0, 0, layer, As, Bs, redS, redQ,
                           nullptr, nullptr);
}

// ---------------- MLP GEMM layer 1: g_x1 @ W1 -> g_y1 ------------------------
__global__ void __launch_bounds__(128, 4)
gemm_l1_kernel(const float* __restrict__ W1) {
    __shared__ __align__(16) float As[2][16][64];
    __shared__ __align__(16) float Bs[2][16][128];
    __shared__ float redS[128];
    __shared__ float redQ[128];
    gemm_body<128, 256, 0>(g_x1, W1, g_y1, NQ, blockIdx.x * 64,
                           blockIdx.y * 128, 2, As, Bs, redS, redQ,
                           nullptr, nullptr);
}

// ---------------- MLP GEMM layer 2: bn1relu(g_y1) @ W2 -> out -----------------
// Layer-2 BN params computed once per block into smem from column stats.
__global__ void __launch_bounds__(128, 4)
gemm_l2_kernel(const float* __restrict__ W2, float* __restrict__ Cext,
               const float* __restrict__ g1, const float* __restrict__ beta1) {
    __shared__ __align__(16) float As[2][16][64];
    __shared__ __align__(16) float Bs[2][16][128];
    __shared__ float redS[128];
    __shared__ float redQ[128];
    __shared__ float s_ts[256];
    __shared__ float s_tt[256];
    int tid = threadIdx.x;
    const float MinvQ = 1.0f / NQ;
#pragma unroll
    for (int it = 0; it < 2; ++it) {
        int c = it * 128 + tid;
        float2 p = bn_st(g_colsum[2 * 256 + c], g_colsq[2 * 256 + c], MinvQ,
                         g1[c], beta1[c]);
        s_ts[c] = p.x;
        s_tt[c] = p.y;
    }
    __syncthreads();
    gemm_body<256, 256, 1>(g_y1, W2, Cext, NQ, blockIdx.x * 64,
                           blockIdx.y * 128, 3, As, Bs, redS, redQ, s_ts, s_tt);
}

// ---------------- final in-place BN + relu on d_out (params inline) ----------
__global__ void final_kernel(float* __restrict__ out,
                             const float* __restrict__ g2,
                             const float* __restrict__ beta2) {
    int i = blockIdx.x * blockDim.x + threadIdx.x;
    if (i >= NQ * 256) return;
    int c = i & 255;
    float2 p = bn_st(g_colsum[3 * 256 + c], g_colsq[3 * 256 + c], 1.0f / NQ,
                     g2[c], beta2[c]);
    float v = out[i];
    out[i] = fmaxf(v * p.x + p.y, 0.f);
}

// ---------------- launch ------------------------------------------------------
extern "C" void kernel_launch(void* const* d_in, const int* in_sizes, int n_in,
                              void* d_out, int out_size) {
    const float* ref_bxyz   = (const float*)d_in[0];
    const float* ref_feat   = (const float*)d_in[1];
    const float* query_bxyz = (const float*)d_in[2];
    const float* query_feat = (const float*)d_in[3];
    const int*   e_ref      = (const int*)d_in[4];
    const int*   e_query    = (const int*)d_in[5];
    const float* Wf0   = (const float*)d_in[6];
    const float* gf0   = (const float*)d_in[7];
    const float* bf0   = (const float*)d_in[8];
    const float* Ws0   = (const float*)d_in[9];
    const float* gs0   = (const float*)d_in[10];
    const float* bs0   = (const float*)d_in[11];
    const float* W1    = (const float*)d_in[12];
    // b1 = d_in[13]: cancels exactly through training-mode BN
    const float* g1    = (const float*)d_in[14];
    const float* beta1 = (const float*)d_in[15];
    const float* W2    = (const float*)d_in[16];
    // b2 = d_in[17]: cancels exactly through training-mode BN
    const float* g2    = (const float*)d_in[18];
    const float* beta2 = (const float*)d_in[19];
    float* out = (float*)d_out;

    zero_kernel<<<(NQ + 255) / 256, 256>>>();
    edge_w_kernel<<<(NE + 255) / 256, 256>>>(ref_bxyz, query_bxyz, e_ref, e_query);

    // fused branch GEMMs (one big grid -> full occupancy) + fused column stats
    gemm01_kernel<<<RB0 + RB1, 128>>>(ref_feat, query_feat, Wf0, Ws0);

    // CSR build + gather (gather computes layer-0/1 BN params inline)
    scan_kernel<<<1, 1024>>>();
    fill_kernel<<<(NE + 255) / 256, 256>>>(e_query);
    gather_kernel<<<(NQ * 32 + 255) / 256, 256>>>(e_ref, gf0, bf0, gs0, bs0);

    // MLP layer 1
    {
        dim3 g2b(RB1, 2);
        gemm_l1_kernel<<<g2b, 128>>>(W1);
    }

    // MLP layer 2 (bn1+relu fused into A-load via smem params), raw y2 -> out
    {
        dim3 g3(RB1, 2);
        gemm_l2_kernel<<<g3, 128>>>(W2, out, g1, beta1);
    }

    // final BN + relu in place (layer-3 params inline)
    final_kernel<<<(NQ * 256 + 255) / 256, 256>>>(out, g2, beta2);
}